// round 11
// baseline (speedup 1.0000x reference)
#include <cuda_runtime.h>
#include <math.h>
#include <float.h>

#define Bc 2
#define Mc 8192
#define Nc (Bc * Mc)
#define KF 16
#define KN 8
#define NB 4096
#define BCAP 64

#define QPB 64                  // queries per block
#define SPLITS 8                // slice-threads per query
#define KTH (QPB * SPLITS)      // 512 threads
#define QBLKS (Mc / QPB)        // 128 per cloud; grid = 256
#define PASS_CANDS 4096         // candidates staged per pass (64KB)
#define SCAP 48                 // survivor cap per (query, slice) segment

// ---- scratch (device globals; no allocation allowed) ----
__device__ int    g_knn[(size_t)Nc * KF];
__device__ double g_acc[8];
__device__ int    g_hist[Bc][NB];
__device__ int    g_pref[Bc][NB];
__device__ int    g_members[Bc][NB * BCAP];
__device__ int    g_nflag;
__device__ int    g_flagq[Nc];
__device__ int2   g_surv[Nc][SPLITS][SCAP];   // (float-bits d, cloud-local idx)
__device__ int    g_cnt[Nc][SPLITS];

// ----- u32 compare-exchange: a=min, b=max -----
__device__ __forceinline__ void cx(unsigned& a, unsigned& b) {
    unsigned lo = min(a, b);
    b = max(a, b);
    a = lo;
}

// Batcher odd-even mergesort n=8 (19 CE), ascending
__device__ __forceinline__ void sort8(unsigned k[8]) {
    cx(k[0],k[1]); cx(k[2],k[3]); cx(k[4],k[5]); cx(k[6],k[7]);
    cx(k[0],k[2]); cx(k[1],k[3]); cx(k[4],k[6]); cx(k[5],k[7]);
    cx(k[1],k[2]); cx(k[5],k[6]);
    cx(k[0],k[4]); cx(k[1],k[5]); cx(k[2],k[6]); cx(k[3],k[7]);
    cx(k[2],k[4]); cx(k[3],k[5]);
    cx(k[1],k[2]); cx(k[3],k[4]); cx(k[5],k[6]);
}

// bitonic cleaner len 8 (12 CE)
__device__ __forceinline__ void clean8(unsigned k[8]) {
    cx(k[0],k[4]); cx(k[1],k[5]); cx(k[2],k[6]); cx(k[3],k[7]);
    cx(k[0],k[2]); cx(k[1],k[3]); cx(k[4],k[6]); cx(k[5],k[7]);
    cx(k[0],k[1]); cx(k[2],k[3]); cx(k[4],k[5]); cx(k[6],k[7]);
}

// ----- (float d, int idx) pair compare-exchange, lexicographic ascending -----
__device__ __forceinline__ void cep(float& ad, int& ai, float& bd, int& bi) {
    bool sw = (bd < ad) || (bd == ad && bi < ai);
    float fl = sw ? bd : ad, fh = sw ? ad : bd;
    int   il = sw ? bi : ai, ih = sw ? ai : bi;
    ad = fl; bd = fh; ai = il; bi = ih;
}

__device__ __forceinline__ void sort8p(float d[8], int x[8]) {
    cep(d[0],x[0],d[1],x[1]); cep(d[2],x[2],d[3],x[3]);
    cep(d[4],x[4],d[5],x[5]); cep(d[6],x[6],d[7],x[7]);
    cep(d[0],x[0],d[2],x[2]); cep(d[1],x[1],d[3],x[3]);
    cep(d[4],x[4],d[6],x[6]); cep(d[5],x[5],d[7],x[7]);
    cep(d[1],x[1],d[2],x[2]); cep(d[5],x[5],d[6],x[6]);
    cep(d[0],x[0],d[4],x[4]); cep(d[1],x[1],d[5],x[5]);
    cep(d[2],x[2],d[6],x[6]); cep(d[3],x[3],d[7],x[7]);
    cep(d[2],x[2],d[4],x[4]); cep(d[3],x[3],d[5],x[5]);
    cep(d[1],x[1],d[2],x[2]); cep(d[3],x[3],d[4],x[4]);
    cep(d[5],x[5],d[6],x[6]);
}

__device__ __forceinline__ void clean16p(float d[16], int x[16]) {
#pragma unroll
    for (int j = 8; j; j >>= 1)
#pragma unroll
        for (int i = 0; i < 16; ++i) {
            int l = i ^ j;
            if (l > i) cep(d[i], x[i], d[l], x[l]);
        }
}

// ================= Kernel A: tau estimate + exhaustive filter =================
extern "C" __global__ void __launch_bounds__(KTH, 2)
knn_kernel(const float* __restrict__ coords) {
    extern __shared__ unsigned char sraw[];
    float4* sh = (float4*)sraw;                        // 64KB staging
    unsigned* tau_sm = (unsigned*)(sraw + PASS_CANDS * 16);  // [QPB]

    const int tid = threadIdx.x;
    const int cloud = blockIdx.x >> 7;
    const int qblk = blockIdx.x & 127;
    const int qLocal = tid & (QPB - 1);
    const int split = tid >> 6;            // warp-uniform

    const float* cb = coords + (size_t)cloud * Mc * 3;
    const int q = qblk * QPB + qLocal;
    const int gq = cloud * Mc + q;

    const float qx = cb[3 * q], qy = cb[3 * q + 1], qz = cb[3 * q + 2];
    const float qw = fmaf(qx, qx, fmaf(qy, qy, qz * qz));
    const float ax = -2.0f * qx, ay = -2.0f * qy, az = -2.0f * qz;

    // ---------- Phase A: keep-8 over a 1/8 subsample (every 8th cand) ----------
    unsigned tk[8];
#pragma unroll
    for (int t = 0; t < 8; ++t) tk[t] = 0xFFFFFFFFu;

#pragma unroll 1
    for (int pass = 0; pass < 2; ++pass) {
        __syncthreads();
        const int wbase = pass * PASS_CANDS;
        for (int i = tid; i < PASS_CANDS; i += KTH) {
            const int jg = wbase + i;
            float x = cb[3 * jg], y = cb[3 * jg + 1], z = cb[3 * jg + 2];
            sh[i] = make_float4(x, y, z, fmaf(x, x, fmaf(y, y, z * z)));
        }
        __syncthreads();

        const float4* ps = sh + (split << 9);
#pragma unroll 1
        for (int b = 0; b < 8; ++b) {      // 8 batches of 8, stride-8 subsample
            unsigned bk[8];
#pragma unroll
            for (int i = 0; i < 8; ++i) {
                float4 c = ps[(b * 8 + i) * 8];
                float d = fmaf(ax, c.x, fmaf(ay, c.y, fmaf(az, c.z, c.w + qw)));
                bk[i] = (__float_as_uint(d) & 0x7FFFF800u) | (unsigned)(b * 8 + i);
            }
            sort8(bk);
#pragma unroll
            for (int i = 0; i < 8; ++i) tk[i] = min(tk[i], bk[7 - i]);
            clean8(tk);
        }
    }

    // ---------- merge 8 sorted-8 keys -> 16th smallest -> tau ----------
    __syncthreads();                       // staging reads done
    unsigned* bufA = (unsigned*)sraw;      // [QPB*68]
    unsigned* bufB = bufA + QPB * 68;      // [QPB*68]
    const int rowA = qLocal * 68 + split * 8;
#pragma unroll
    for (int t = 0; t < 8; ++t) bufA[rowA + t] = tk[t];
    __syncthreads();

#define MRGU(SRC_A, SRC_B, LEN, DSTSTMT)                                      \
    {                                                                         \
        int ii = 0, jj = 0;                                                   \
        _Pragma("unroll 1")                                                   \
        for (int r = 0; r < 16; ++r) {                                        \
            unsigned a = (SRC_A)[min(ii, (LEN) - 1)];                         \
            unsigned b = (SRC_B)[min(jj, (LEN) - 1)];                         \
            bool takeA = (jj >= (LEN)) || ((ii < (LEN)) && (a <= b));         \
            unsigned o = takeA ? a : b;                                       \
            ii += takeA; jj += !takeA;                                        \
            DSTSTMT;                                                          \
        }                                                                     \
    }

    if (split < 4) {
        const unsigned* sa = bufA + qLocal * 68 + split * 16;
        unsigned* dst = bufB + qLocal * 68 + split * 16;
        MRGU(sa, sa + 8, 8, dst[r] = o);
    }
    __syncthreads();
    if (split < 2) {
        const unsigned* sa = bufB + qLocal * 68 + split * 32;
        unsigned* dst = bufA + qLocal * 68 + split * 16;
        MRGU(sa, sa + 16, 16, dst[r] = o);
    }
    __syncthreads();
    if (split == 0) {
        const unsigned* sa = bufA + qLocal * 68;
        unsigned last = 0;
        MRGU(sa, sa + 16, 16, last = o);
        tau_sm[qLocal] = last | 0x7FFu;    // bin-top: valid upper bound of d16
    }
    __syncthreads();
    const float tauf = __uint_as_float(tau_sm[qLocal]);

    // ---------- Phase B: exhaustive filter, survivors to private segment ----------
    int cnt = 0;
    int2* seg = &g_surv[gq][split][0];
#pragma unroll 1
    for (int pass = 0; pass < 2; ++pass) {
        __syncthreads();                   // merge bufs / prior staging done
        const int wbase = pass * PASS_CANDS;
        for (int i = tid; i < PASS_CANDS; i += KTH) {
            const int jg = wbase + i;
            float x = cb[3 * jg], y = cb[3 * jg + 1], z = cb[3 * jg + 2];
            sh[i] = make_float4(x, y, z, fmaf(x, x, fmaf(y, y, z * z)));
        }
        __syncthreads();

        const float4* ps = sh + (split << 9);
        const int gbase = wbase + (split << 9);
#pragma unroll 8
        for (int j = 0; j < 512; ++j) {
            float4 c = ps[j];
            float d = fmaf(ax, c.x, fmaf(ay, c.y, fmaf(az, c.z, c.w + qw)));
            if (d <= tauf) {
                if (cnt < SCAP)
                    seg[cnt] = make_int2(__float_as_int(d), gbase + j);
                ++cnt;
            }
        }
    }
    g_cnt[gq][split] = cnt;
}

// ================= select: exact top-16 of survivors =================
__global__ void __launch_bounds__(128)
select_kernel() {
    const int gq = blockIdx.x * 128 + threadIdx.x;
    const int goff = (gq >> 13) << 13;

    float td[16]; int ti[16];
#pragma unroll
    for (int t = 0; t < 16; ++t) { td[t] = __int_as_float(0x7F800000); ti[t] = 0x7FFFFFFF; }

    bool ovf = false;
#pragma unroll 1
    for (int s = 0; s < SPLITS; ++s) {
        int cn = g_cnt[gq][s];
        if (cn > SCAP) { ovf = true; cn = SCAP; }
        const int2* sp = &g_surv[gq][s][0];
#pragma unroll 1
        for (int k = 0; k < cn; k += 8) {
            float bd[8]; int bi[8];
#pragma unroll
            for (int i = 0; i < 8; ++i) {
                bool v = (k + i) < cn;
                int2 sv = v ? sp[k + i] : make_int2(0x7F800000, 0x7FFFFFFF);
                bd[i] = __int_as_float(sv.x);
                bi[i] = sv.y;
            }
            sort8p(bd, bi);
            // halver: top-16 of (sorted16 td ∪ sorted8 bd) -> bitonic -> clean
#pragma unroll
            for (int i = 0; i < 8; ++i) cep(td[8 + i], ti[8 + i], bd[7 - i], bi[7 - i]);
            clean16p(td, ti);
        }
    }

    if (!ovf) {
        int* out = g_knn + (size_t)gq * KF;
#pragma unroll
        for (int t = 0; t < 16; ++t) out[t] = goff + ti[t];
    } else {
        int slot = atomicAdd(&g_nflag, 1);
        g_flagq[slot] = gq;
    }
}

// ============ exact fallback for overflowed queries (rare) ============
__device__ __forceinline__ void clean16(unsigned k[16]) {
#pragma unroll
    for (int j = 8; j; j >>= 1)
#pragma unroll
        for (int i = 0; i < 16; ++i) {
            int l = i ^ j;
            if (l > i) cx(k[i], k[l]);
        }
}

#define FB_BLOCKS 296
#define FB_WARPS 8
__global__ void __launch_bounds__(FB_WARPS * 32)
fallback_kernel(const float* __restrict__ coords) {
    __shared__ unsigned S[FB_WARPS][32][17];
    const int w = threadIdx.x >> 5;
    const int lane = threadIdx.x & 31;
    const int nf = g_nflag;

    for (int f = blockIdx.x * FB_WARPS + w; f < nf; f += FB_BLOCKS * FB_WARPS) {
        const int gq = g_flagq[f];
        const int cloud = gq >> 13;
        const int q = gq & (Mc - 1);
        const float* cb = coords + (size_t)cloud * Mc * 3;
        const float4* cp = (const float4*)cb;
        const float qx = cb[3 * q], qy = cb[3 * q + 1], qz = cb[3 * q + 2];

        unsigned tk[16];
#pragma unroll
        for (int t = 0; t < 16; ++t) tk[t] = 0xFFFFFFFFu;

#pragma unroll 1
        for (int b = 0; b < 32; ++b) {
            const int j0 = lane * 256 + b * 8;
            const float4* p = cp + ((3 * j0) >> 2);
            float4 A = p[0], Bv = p[1], C = p[2], D = p[3], E = p[4], F = p[5];
            float xs[8] = {A.x, A.w, Bv.z, C.y, D.x, D.w, E.z, F.y};
            float ys[8] = {A.y, Bv.x, Bv.w, C.z, D.y, E.x, E.w, F.z};
            float zs[8] = {A.z, Bv.y, C.x, C.w, D.z, E.y, F.x, F.w};
            unsigned bk[8];
#pragma unroll
            for (int i = 0; i < 8; ++i) {
                float dx = xs[i] - qx, dy = ys[i] - qy, dz = zs[i] - qz;
                float d = fmaf(dz, dz, fmaf(dy, dy, dx * dx));
                bk[i] = (__float_as_uint(d) & 0xFFFFE000u) | (unsigned)(j0 + i);
            }
            sort8(bk);
#pragma unroll
            for (int i = 0; i < 8; ++i) tk[15 - i] = min(tk[15 - i], bk[i]);
            clean16(tk);
        }

#pragma unroll
        for (int t = 0; t < 16; ++t) S[w][lane][t] = tk[t];
        __syncwarp();
#pragma unroll
        for (int s = 1; s < 32; s <<= 1) {
            if ((lane & (2 * s - 1)) == 0) {
                unsigned ok[16];
#pragma unroll
                for (int t = 0; t < 16; ++t) ok[t] = S[w][lane + s][t];
#pragma unroll
                for (int t = 0; t < 16; ++t) tk[t] = min(tk[t], ok[15 - t]);
                clean16(tk);
#pragma unroll
                for (int t = 0; t < 16; ++t) S[w][lane][t] = tk[t];
            }
            __syncwarp();
        }
        if (lane == 0) {
            int* out = g_knn + (size_t)gq * KF;
            const int goff = cloud * Mc;
#pragma unroll
            for (int t = 0; t < 16; ++t) out[t] = goff + (int)(tk[t] & 0x1FFFu);
        }
        __syncwarp();
    }
}

// ================= rank bucketing (exact, replaces sort) =================
__global__ void zero_kernel() {
    const int t = blockIdx.x * blockDim.x + threadIdx.x;
    if (t < 8) g_acc[t] = 0.0;
    if (t == 8) g_nflag = 0;
    for (int i = t; i < Bc * NB; i += gridDim.x * blockDim.x)
        ((int*)g_hist)[i] = 0;
}

__global__ void rank_build_kernel(const float* __restrict__ scores) {
    const int i = blockIdx.x * blockDim.x + threadIdx.x;
    if (i >= Nc) return;
    const int cloud = i >> 13;
    const int local = i & (Mc - 1);
    const float s = scores[i];
    int b = (int)(s * (float)NB);
    b = b < 0 ? 0 : (b > NB - 1 ? NB - 1 : b);
    const int slot = atomicAdd(&g_hist[cloud][b], 1);
    if (slot < BCAP) g_members[cloud][b * BCAP + slot] = local;
}

__global__ void prefix_kernel() {
    __shared__ int sc[1024];
    const int cloud = blockIdx.x;
    const int t = threadIdx.x;
    const int base = t * 4;
    int h0 = g_hist[cloud][base + 0];
    int h1 = g_hist[cloud][base + 1];
    int h2 = g_hist[cloud][base + 2];
    int h3 = g_hist[cloud][base + 3];
    int sum = h0 + h1 + h2 + h3;
    sc[t] = sum;
    __syncthreads();
    for (int off = 1; off < 1024; off <<= 1) {
        int v = (t >= off) ? sc[t - off] : 0;
        __syncthreads();
        sc[t] += v;
        __syncthreads();
    }
    int excl = sc[t] - sum;
    g_pref[cloud][base + 0] = excl; excl += h0;
    g_pref[cloud][base + 1] = excl; excl += h1;
    g_pref[cloud][base + 2] = excl; excl += h2;
    g_pref[cloud][base + 3] = excl;
}

// ================= per-point losses (+ rank dist loss) =================
__global__ void loss_points_kernel(const float* __restrict__ scores,
                                   const float* __restrict__ coords) {
    const int i = blockIdx.x * blockDim.x + threadIdx.x;
    double acc[6] = {0, 0, 0, 0, 0, 0};

    {
        const float si = scores[i];
        const float xi = coords[3 * i], yi = coords[3 * i + 1], zi = coords[3 * i + 2];
        float nsum = 0.0f;
        const int* nb = g_knn + (size_t)i * KF;
#pragma unroll
        for (int r = 0; r < KF; ++r) {
            const int n = nb[r];
            const float sn = scores[n];
            const float sd = fabsf(si - sn);
            const float x = (1.0f - sd) * 2.0f;
            const float sig = 1.0f / (1.0f + expf(-x));
            if (r < KN) {
                const float dx = xi - coords[3 * n];
                const float dy = yi - coords[3 * n + 1];
                const float dz = zi - coords[3 * n + 2];
                const float dist = sqrtf(dx * dx + dy * dy + dz * dz);
                const float w = expf(-dist * 10.0f);
                acc[0] += (double)(w * sd * sd);
                acc[1] += (double)w;
                acc[2] += (double)logf(sig + 1e-8f);
                nsum += sn;
            } else {
                acc[3] += (double)logf(1.0f - sig + 1e-8f);
            }
        }
        const float dm = si - nsum * 0.125f;
        acc[4] = (double)(dm * dm);

        const int cloud = i >> 13;
        const int local = i & (Mc - 1);
        int b = (int)(si * (float)NB);
        b = b < 0 ? 0 : (b > NB - 1 ? NB - 1 : b);
        int cnt = g_hist[cloud][b];
        cnt = cnt > BCAP ? BCAP : cnt;
        int r = 0;
        const int* mem = &g_members[cloud][b * BCAP];
        for (int k = 0; k < cnt; ++k) {
            const int m = mem[k];
            const float sm = scores[(cloud << 13) + m];
            r += (sm < si) || (sm == si && m < local);
        }
        const int rank = g_pref[cloud][b] + r;
        const float df = si - (float)rank * (1.0f / (float)(Mc - 1));
        acc[5] = (double)(df * df);
    }

    const int lane = threadIdx.x & 31;
    const int wid = threadIdx.x >> 5;
#pragma unroll
    for (int k = 0; k < 6; ++k)
#pragma unroll
        for (int o = 16; o; o >>= 1)
            acc[k] += __shfl_down_sync(0xffffffffu, acc[k], o);

    __shared__ double red[8][6];
    if (lane == 0)
#pragma unroll
        for (int k = 0; k < 6; ++k) red[wid][k] = acc[k];
    __syncthreads();
    if (wid == 0 && lane < 6) {
        double s = 0.0;
#pragma unroll
        for (int w = 0; w < 8; ++w) s += red[w][lane];
        atomicAdd(&g_acc[lane], s);
    }
}

// ================= finalize =================
__global__ void finalize_kernel(float* out) {
    const double l_loc = g_acc[0] / fmax(g_acc[1], 1e-8);
    const double l_pos = -g_acc[2] / (double)((size_t)Nc * KN);
    const double l_neg = -g_acc[3] / (double)((size_t)Nc * KN);
    const double l_con = l_pos + l_neg;
    const double l_smooth = g_acc[4] / (double)Nc;
    const double l_dist = g_acc[5] / (double)Nc;
    out[0] = (float)(1.0 * l_loc + 0.5 * l_con + 0.3 * l_dist + 0.2 * l_smooth);
}

extern "C" void kernel_launch(void* const* d_in, const int* in_sizes, int n_in,
                              void* d_out, int out_size) {
    const float* scores = (const float*)d_in[0];
    const float* coords = (const float*)d_in[1];
    (void)in_sizes; (void)n_in; (void)out_size;

    const int KNN_SMEM = PASS_CANDS * 16 + QPB * (int)sizeof(unsigned) + 128;
    cudaFuncSetAttribute(knn_kernel,
                         cudaFuncAttributeMaxDynamicSharedMemorySize, KNN_SMEM);

    zero_kernel<<<16, 1024>>>();
    rank_build_kernel<<<Nc / 256, 256>>>(scores);
    prefix_kernel<<<Bc, 1024>>>();
    knn_kernel<<<Bc * QBLKS, KTH, KNN_SMEM>>>(coords);
    select_kernel<<<Nc / 128, 128>>>();
    fallback_kernel<<<FB_BLOCKS, FB_WARPS * 32>>>(coords);
    loss_points_kernel<<<Nc / 256, 256>>>(scores, coords);
    finalize_kernel<<<1, 1>>>((float*)d_out);
}

// round 12
// speedup vs baseline: 1.5033x; 1.5033x over previous
#include <cuda_runtime.h>
#include <math.h>
#include <float.h>

#define Bc 2
#define Mc 8192
#define Nc (Bc * Mc)
#define KF 16
#define KN 8
#define NB 4096
#define BCAP 64

#define QPB 64                  // queries per block (knn)
#define SPLITS 8                // slice-threads per query
#define KTH (QPB * SPLITS)      // 512 threads
#define QBLKS (Mc / QPB)        // 128 per cloud; grid = 256
#define PASS_CANDS 4096         // candidates staged per pass (64KB)
#define SCAP 48                 // survivor cap per (query, slice) segment

// ---- scratch (device globals; no allocation allowed) ----
__device__ int      g_knn[(size_t)Nc * KF];
__device__ double   g_acc[8];
__device__ int      g_hist[Bc][NB];
__device__ int      g_pref[Bc][NB];
__device__ int      g_members[Bc][NB * BCAP];
__device__ int      g_nflag;
__device__ int      g_flagq[Nc];
__device__ unsigned g_survk[Nc][SPLITS][SCAP];  // (d18 sign-cleared)<<13 | idx13
__device__ int      g_cnt[Nc][SPLITS];

// ----- u32 compare-exchange: a=min, b=max -----
__device__ __forceinline__ void cx(unsigned& a, unsigned& b) {
    unsigned lo = min(a, b);
    b = max(a, b);
    a = lo;
}

// Batcher odd-even mergesort n=8 (19 CE), ascending
__device__ __forceinline__ void sort8(unsigned k[8]) {
    cx(k[0],k[1]); cx(k[2],k[3]); cx(k[4],k[5]); cx(k[6],k[7]);
    cx(k[0],k[2]); cx(k[1],k[3]); cx(k[4],k[6]); cx(k[5],k[7]);
    cx(k[1],k[2]); cx(k[5],k[6]);
    cx(k[0],k[4]); cx(k[1],k[5]); cx(k[2],k[6]); cx(k[3],k[7]);
    cx(k[2],k[4]); cx(k[3],k[5]);
    cx(k[1],k[2]); cx(k[3],k[4]); cx(k[5],k[6]);
}

// bitonic cleaner len 8 (12 CE)
__device__ __forceinline__ void clean8(unsigned k[8]) {
    cx(k[0],k[4]); cx(k[1],k[5]); cx(k[2],k[6]); cx(k[3],k[7]);
    cx(k[0],k[2]); cx(k[1],k[3]); cx(k[4],k[6]); cx(k[5],k[7]);
    cx(k[0],k[1]); cx(k[2],k[3]); cx(k[4],k[5]); cx(k[6],k[7]);
}

// bitonic cleaner len 16 (32 CE)
__device__ __forceinline__ void clean16(unsigned k[16]) {
#pragma unroll
    for (int j = 8; j; j >>= 1)
#pragma unroll
        for (int i = 0; i < 16; ++i) {
            int l = i ^ j;
            if (l > i) cx(k[i], k[l]);
        }
}

// 2-way serial merge of sorted u32 lists -> 16 smallest
#define MRGU(SRC_A, SRC_B, LEN, DSTSTMT)                                      \
    {                                                                         \
        int ii = 0, jj = 0;                                                   \
        _Pragma("unroll 1")                                                   \
        for (int r = 0; r < 16; ++r) {                                        \
            unsigned a = (SRC_A)[min(ii, (LEN) - 1)];                         \
            unsigned b = (SRC_B)[min(jj, (LEN) - 1)];                         \
            bool takeA = (jj >= (LEN)) || ((ii < (LEN)) && (a <= b));         \
            unsigned o = takeA ? a : b;                                       \
            ii += takeA; jj += !takeA;                                        \
            DSTSTMT;                                                          \
        }                                                                     \
    }

// ================= Kernel A: tau estimate + exhaustive filter =================
extern "C" __global__ void __launch_bounds__(KTH, 2)
knn_kernel(const float* __restrict__ coords) {
    extern __shared__ unsigned char sraw[];
    float4* sh = (float4*)sraw;                        // 64KB staging
    unsigned* tau_sm = (unsigned*)(sraw + PASS_CANDS * 16);  // [QPB]

    const int tid = threadIdx.x;
    const int cloud = blockIdx.x >> 7;
    const int qblk = blockIdx.x & 127;
    const int qLocal = tid & (QPB - 1);
    const int split = tid >> 6;            // warp-uniform

    const float* cb = coords + (size_t)cloud * Mc * 3;
    const int q = qblk * QPB + qLocal;
    const int gq = cloud * Mc + q;

    const float qx = cb[3 * q], qy = cb[3 * q + 1], qz = cb[3 * q + 2];
    const float qw = fmaf(qx, qx, fmaf(qy, qy, qz * qz));
    const float ax = -2.0f * qx, ay = -2.0f * qy, az = -2.0f * qz;

    // ---------- Phase A: keep-8 over a 1/8 subsample ----------
    unsigned tk[8];
#pragma unroll
    for (int t = 0; t < 8; ++t) tk[t] = 0xFFFFFFFFu;

#pragma unroll 1
    for (int pass = 0; pass < 2; ++pass) {
        __syncthreads();
        const int wbase = pass * PASS_CANDS;
        for (int i = tid; i < PASS_CANDS; i += KTH) {
            const int jg = wbase + i;
            float x = cb[3 * jg], y = cb[3 * jg + 1], z = cb[3 * jg + 2];
            sh[i] = make_float4(x, y, z, fmaf(x, x, fmaf(y, y, z * z)));
        }
        __syncthreads();

        const float4* ps = sh + (split << 9);
#pragma unroll 1
        for (int b = 0; b < 8; ++b) {
            unsigned bk[8];
#pragma unroll
            for (int i = 0; i < 8; ++i) {
                float4 c = ps[(b * 8 + i) * 8];
                float d = fmaf(ax, c.x, fmaf(ay, c.y, fmaf(az, c.z, c.w + qw)));
                bk[i] = (__float_as_uint(d) & 0x7FFFF800u) | (unsigned)(b * 8 + i);
            }
            sort8(bk);
#pragma unroll
            for (int i = 0; i < 8; ++i) tk[i] = min(tk[i], bk[7 - i]);
            clean8(tk);
        }
    }

    // ---------- merge 8 sorted-8 keys -> 16th smallest -> tau ----------
    __syncthreads();
    unsigned* bufA = (unsigned*)sraw;      // [QPB*68]
    unsigned* bufB = bufA + QPB * 68;      // [QPB*68]
    const int rowA = qLocal * 68 + split * 8;
#pragma unroll
    for (int t = 0; t < 8; ++t) bufA[rowA + t] = tk[t];
    __syncthreads();

    if (split < 4) {
        const unsigned* sa = bufA + qLocal * 68 + split * 16;
        unsigned* dst = bufB + qLocal * 68 + split * 16;
        MRGU(sa, sa + 8, 8, dst[r] = o);
    }
    __syncthreads();
    if (split < 2) {
        const unsigned* sa = bufB + qLocal * 68 + split * 32;
        unsigned* dst = bufA + qLocal * 68 + split * 16;
        MRGU(sa, sa + 16, 16, dst[r] = o);
    }
    __syncthreads();
    if (split == 0) {
        const unsigned* sa = bufA + qLocal * 68;
        unsigned last = 0;
        MRGU(sa, sa + 16, 16, last = o);
        tau_sm[qLocal] = last | 0x7FFu;    // bin-top: valid upper bound of d16
    }
    __syncthreads();
    const float tauf = __uint_as_float(tau_sm[qLocal]);

    // ---------- Phase B: exhaustive filter, packed-key survivors ----------
    int cnt = 0;
    unsigned* seg = &g_survk[gq][split][0];
#pragma unroll 1
    for (int pass = 0; pass < 2; ++pass) {
        __syncthreads();
        const int wbase = pass * PASS_CANDS;
        for (int i = tid; i < PASS_CANDS; i += KTH) {
            const int jg = wbase + i;
            float x = cb[3 * jg], y = cb[3 * jg + 1], z = cb[3 * jg + 2];
            sh[i] = make_float4(x, y, z, fmaf(x, x, fmaf(y, y, z * z)));
        }
        __syncthreads();

        const float4* ps = sh + (split << 9);
        const int gbase = wbase + (split << 9);
#pragma unroll 8
        for (int j = 0; j < 512; ++j) {
            float4 c = ps[j];
            float d = fmaf(ax, c.x, fmaf(ay, c.y, fmaf(az, c.z, c.w + qw)));
            if (d <= tauf) {
                if (cnt < SCAP)
                    seg[cnt] = ((__float_as_uint(d) & 0x7FFFE000u))
                             | (unsigned)(gbase + j);
                ++cnt;
            }
        }
    }
    g_cnt[gq][split] = cnt;
}

// ================= select: top-16 of survivors (8 threads/query) =================
extern "C" __global__ void __launch_bounds__(KTH, 2)
select_kernel() {
    extern __shared__ unsigned char sraw[];
    unsigned* bufA = (unsigned*)sraw;              // [QPB][136]: 8 segs x 16
    unsigned* bufB = bufA + QPB * 136;             // [QPB][68] : 4 segs x 16
    int* ovf = (int*)(bufB + QPB * 68);            // [QPB]

    const int tid = threadIdx.x;
    const int qLocal = tid & (QPB - 1);
    const int split = tid >> 6;
    const int gq = blockIdx.x * QPB + qLocal;
    const int goff = (gq >> 13) << 13;

    if (split == 0) ovf[qLocal] = 0;
    __syncthreads();

    int cn = g_cnt[gq][split];
    if (cn > SCAP) { ovf[qLocal] = 1; cn = SCAP; }
    const unsigned* seg = &g_survk[gq][split][0];

    unsigned tk[16];
#pragma unroll
    for (int t = 0; t < 16; ++t) tk[t] = 0xFFFFFFFFu;

#pragma unroll 1
    for (int k = 0; k < cn; k += 8) {
        unsigned bk[8];
#pragma unroll
        for (int i = 0; i < 8; ++i)
            bk[i] = (k + i < cn) ? seg[k + i] : 0xFFFFFFFFu;
        sort8(bk);
#pragma unroll
        for (int i = 0; i < 8; ++i) tk[15 - i] = min(tk[15 - i], bk[i]);
        clean16(tk);
    }

    const int rowA = qLocal * 136 + split * 16;
#pragma unroll
    for (int t = 0; t < 16; ++t) bufA[rowA + t] = tk[t];
    __syncthreads();

    if (split < 4) {   // round 1: 8 sorted-16 -> 4
        const unsigned* sa = bufA + qLocal * 136 + split * 32;
        unsigned* dst = bufB + qLocal * 68 + split * 16;
        MRGU(sa, sa + 16, 16, dst[r] = o);
    }
    __syncthreads();
    if (split < 2) {   // round 2: 4 -> 2
        const unsigned* sa = bufB + qLocal * 68 + split * 32;
        unsigned* dst = bufA + qLocal * 136 + split * 16;
        MRGU(sa, sa + 16, 16, dst[r] = o);
    }
    __syncthreads();
    if (split == 0) {  // round 3: 2 -> 1, write
        int* out = g_knn + (size_t)gq * KF;
        const unsigned* sa = bufA + qLocal * 136;
        MRGU(sa, sa + 16, 16, out[r] = goff + (int)(o & 0x1FFFu));
        if (ovf[qLocal]) {
            int slot = atomicAdd(&g_nflag, 1);
            g_flagq[slot] = gq;
        }
    }
}

// ============ exact fallback for overflowed queries (rare) ============
#define FB_BLOCKS 296
#define FB_WARPS 8
__global__ void __launch_bounds__(FB_WARPS * 32)
fallback_kernel(const float* __restrict__ coords) {
    __shared__ unsigned S[FB_WARPS][32][17];
    const int w = threadIdx.x >> 5;
    const int lane = threadIdx.x & 31;
    const int nf = g_nflag;

    for (int f = blockIdx.x * FB_WARPS + w; f < nf; f += FB_BLOCKS * FB_WARPS) {
        const int gq = g_flagq[f];
        const int cloud = gq >> 13;
        const int q = gq & (Mc - 1);
        const float* cb = coords + (size_t)cloud * Mc * 3;
        const float4* cp = (const float4*)cb;
        const float qx = cb[3 * q], qy = cb[3 * q + 1], qz = cb[3 * q + 2];

        unsigned tk[16];
#pragma unroll
        for (int t = 0; t < 16; ++t) tk[t] = 0xFFFFFFFFu;

#pragma unroll 1
        for (int b = 0; b < 32; ++b) {
            const int j0 = lane * 256 + b * 8;
            const float4* p = cp + ((3 * j0) >> 2);
            float4 A = p[0], Bv = p[1], C = p[2], D = p[3], E = p[4], F = p[5];
            float xs[8] = {A.x, A.w, Bv.z, C.y, D.x, D.w, E.z, F.y};
            float ys[8] = {A.y, Bv.x, Bv.w, C.z, D.y, E.x, E.w, F.z};
            float zs[8] = {A.z, Bv.y, C.x, C.w, D.z, E.y, F.x, F.w};
            unsigned bk[8];
#pragma unroll
            for (int i = 0; i < 8; ++i) {
                float dx = xs[i] - qx, dy = ys[i] - qy, dz = zs[i] - qz;
                float d = fmaf(dz, dz, fmaf(dy, dy, dx * dx));
                bk[i] = (__float_as_uint(d) & 0xFFFFE000u) | (unsigned)(j0 + i);
            }
            sort8(bk);
#pragma unroll
            for (int i = 0; i < 8; ++i) tk[15 - i] = min(tk[15 - i], bk[i]);
            clean16(tk);
        }

#pragma unroll
        for (int t = 0; t < 16; ++t) S[w][lane][t] = tk[t];
        __syncwarp();
#pragma unroll
        for (int s = 1; s < 32; s <<= 1) {
            if ((lane & (2 * s - 1)) == 0) {
                unsigned ok[16];
#pragma unroll
                for (int t = 0; t < 16; ++t) ok[t] = S[w][lane + s][t];
#pragma unroll
                for (int t = 0; t < 16; ++t) tk[t] = min(tk[t], ok[15 - t]);
                clean16(tk);
#pragma unroll
                for (int t = 0; t < 16; ++t) S[w][lane][t] = tk[t];
            }
            __syncwarp();
        }
        if (lane == 0) {
            int* out = g_knn + (size_t)gq * KF;
            const int goff = cloud * Mc;
#pragma unroll
            for (int t = 0; t < 16; ++t) out[t] = goff + (int)(tk[t] & 0x1FFFu);
        }
        __syncwarp();
    }
}

// ================= rank bucketing (exact, replaces sort) =================
__global__ void zero_kernel() {
    const int t = blockIdx.x * blockDim.x + threadIdx.x;
    if (t < 8) g_acc[t] = 0.0;
    if (t == 8) g_nflag = 0;
    for (int i = t; i < Bc * NB; i += gridDim.x * blockDim.x)
        ((int*)g_hist)[i] = 0;
}

__global__ void rank_build_kernel(const float* __restrict__ scores) {
    const int i = blockIdx.x * blockDim.x + threadIdx.x;
    if (i >= Nc) return;
    const int cloud = i >> 13;
    const int local = i & (Mc - 1);
    const float s = scores[i];
    int b = (int)(s * (float)NB);
    b = b < 0 ? 0 : (b > NB - 1 ? NB - 1 : b);
    const int slot = atomicAdd(&g_hist[cloud][b], 1);
    if (slot < BCAP) g_members[cloud][b * BCAP + slot] = local;
}

__global__ void prefix_kernel() {
    __shared__ int sc[1024];
    const int cloud = blockIdx.x;
    const int t = threadIdx.x;
    const int base = t * 4;
    int h0 = g_hist[cloud][base + 0];
    int h1 = g_hist[cloud][base + 1];
    int h2 = g_hist[cloud][base + 2];
    int h3 = g_hist[cloud][base + 3];
    int sum = h0 + h1 + h2 + h3;
    sc[t] = sum;
    __syncthreads();
    for (int off = 1; off < 1024; off <<= 1) {
        int v = (t >= off) ? sc[t - off] : 0;
        __syncthreads();
        sc[t] += v;
        __syncthreads();
    }
    int excl = sc[t] - sum;
    g_pref[cloud][base + 0] = excl; excl += h0;
    g_pref[cloud][base + 1] = excl; excl += h1;
    g_pref[cloud][base + 2] = excl; excl += h2;
    g_pref[cloud][base + 3] = excl;
}

// ================= per-point losses (+ rank dist loss) =================
__global__ void loss_points_kernel(const float* __restrict__ scores,
                                   const float* __restrict__ coords) {
    const int i = blockIdx.x * blockDim.x + threadIdx.x;
    double acc[6] = {0, 0, 0, 0, 0, 0};

    {
        const float si = scores[i];
        const float xi = coords[3 * i], yi = coords[3 * i + 1], zi = coords[3 * i + 2];
        float nsum = 0.0f;
        const int* nb = g_knn + (size_t)i * KF;
#pragma unroll
        for (int r = 0; r < KF; ++r) {
            const int n = nb[r];
            const float sn = scores[n];
            const float sd = fabsf(si - sn);
            const float x = (1.0f - sd) * 2.0f;
            const float sig = 1.0f / (1.0f + expf(-x));
            if (r < KN) {
                const float dx = xi - coords[3 * n];
                const float dy = yi - coords[3 * n + 1];
                const float dz = zi - coords[3 * n + 2];
                const float dist = sqrtf(dx * dx + dy * dy + dz * dz);
                const float w = expf(-dist * 10.0f);
                acc[0] += (double)(w * sd * sd);
                acc[1] += (double)w;
                acc[2] += (double)logf(sig + 1e-8f);
                nsum += sn;
            } else {
                acc[3] += (double)logf(1.0f - sig + 1e-8f);
            }
        }
        const float dm = si - nsum * 0.125f;
        acc[4] = (double)(dm * dm);

        const int cloud = i >> 13;
        const int local = i & (Mc - 1);
        int b = (int)(si * (float)NB);
        b = b < 0 ? 0 : (b > NB - 1 ? NB - 1 : b);
        int cnt = g_hist[cloud][b];
        cnt = cnt > BCAP ? BCAP : cnt;
        int r = 0;
        const int* mem = &g_members[cloud][b * BCAP];
        for (int k = 0; k < cnt; ++k) {
            const int m = mem[k];
            const float sm = scores[(cloud << 13) + m];
            r += (sm < si) || (sm == si && m < local);
        }
        const int rank = g_pref[cloud][b] + r;
        const float df = si - (float)rank * (1.0f / (float)(Mc - 1));
        acc[5] = (double)(df * df);
    }

    const int lane = threadIdx.x & 31;
    const int wid = threadIdx.x >> 5;
#pragma unroll
    for (int k = 0; k < 6; ++k)
#pragma unroll
        for (int o = 16; o; o >>= 1)
            acc[k] += __shfl_down_sync(0xffffffffu, acc[k], o);

    __shared__ double red[8][6];
    if (lane == 0)
#pragma unroll
        for (int k = 0; k < 6; ++k) red[wid][k] = acc[k];
    __syncthreads();
    if (wid == 0 && lane < 6) {
        double s = 0.0;
#pragma unroll
        for (int w = 0; w < 8; ++w) s += red[w][lane];
        atomicAdd(&g_acc[lane], s);
    }
}

// ================= finalize =================
__global__ void finalize_kernel(float* out) {
    const double l_loc = g_acc[0] / fmax(g_acc[1], 1e-8);
    const double l_pos = -g_acc[2] / (double)((size_t)Nc * KN);
    const double l_neg = -g_acc[3] / (double)((size_t)Nc * KN);
    const double l_con = l_pos + l_neg;
    const double l_smooth = g_acc[4] / (double)Nc;
    const double l_dist = g_acc[5] / (double)Nc;
    out[0] = (float)(1.0 * l_loc + 0.5 * l_con + 0.3 * l_dist + 0.2 * l_smooth);
}

extern "C" void kernel_launch(void* const* d_in, const int* in_sizes, int n_in,
                              void* d_out, int out_size) {
    const float* scores = (const float*)d_in[0];
    const float* coords = (const float*)d_in[1];
    (void)in_sizes; (void)n_in; (void)out_size;

    const int KNN_SMEM = PASS_CANDS * 16 + QPB * (int)sizeof(unsigned) + 128;
    cudaFuncSetAttribute(knn_kernel,
                         cudaFuncAttributeMaxDynamicSharedMemorySize, KNN_SMEM);
    const int SEL_SMEM = (QPB * 136 + QPB * 68) * (int)sizeof(unsigned)
                       + QPB * (int)sizeof(int);
    cudaFuncSetAttribute(select_kernel,
                         cudaFuncAttributeMaxDynamicSharedMemorySize, SEL_SMEM);

    zero_kernel<<<16, 1024>>>();
    rank_build_kernel<<<Nc / 256, 256>>>(scores);
    prefix_kernel<<<Bc, 1024>>>();
    knn_kernel<<<Bc * QBLKS, KTH, KNN_SMEM>>>(coords);
    select_kernel<<<Nc / QPB, KTH, SEL_SMEM>>>();
    fallback_kernel<<<FB_BLOCKS, FB_WARPS * 32>>>(coords);
    loss_points_kernel<<<Nc / 256, 256>>>(scores, coords);
    finalize_kernel<<<1, 1>>>((float*)d_out);
}

// round 13
// speedup vs baseline: 1.5555x; 1.0347x over previous
#include <cuda_runtime.h>
#include <math.h>
#include <float.h>

#define Bc 2
#define Mc 8192
#define Nc (Bc * Mc)
#define KF 16
#define KN 8
#define NB 4096
#define BCAP 64

#define QPB 64                  // queries per block (knn/select)
#define SPLITS 8                // slice-threads per query
#define KTH (QPB * SPLITS)      // 512 threads
#define QBLKS (Mc / QPB)        // 128 per cloud; grid = 256
#define PASS_CANDS 4096         // candidates staged per pass (64KB SoA)
#define SCAP 48                 // survivor cap per (query, slice) segment

// ---- scratch (device globals; no allocation allowed) ----
__device__ int      g_knn[(size_t)Nc * KF];
__device__ double   g_acc[8];
__device__ int      g_hist[Bc][NB];
__device__ int      g_pref[Bc][NB];
__device__ int      g_members[Bc][NB * BCAP];
__device__ int      g_nflag;
__device__ int      g_flagq[Nc];
__device__ unsigned g_survk[Nc][SPLITS][SCAP];  // (d18 sign-cleared)<<13 | idx13
__device__ int      g_cnt[Nc][SPLITS];

// ----- f32x2 packed helpers (sm_103a) -----
__device__ __forceinline__ unsigned long long pack2(float v) {
    unsigned long long r;
    asm("mov.b64 %0, {%1, %1};" : "=l"(r) : "f"(v));
    return r;
}
__device__ __forceinline__ void unpack2(unsigned long long v, float& lo, float& hi) {
    asm("mov.b64 {%0, %1}, %2;" : "=f"(lo), "=f"(hi) : "l"(v));
}
__device__ __forceinline__ unsigned long long fma2(unsigned long long a,
                                                   unsigned long long b,
                                                   unsigned long long c) {
    unsigned long long r;
    asm("fma.rn.f32x2 %0, %1, %2, %3;" : "=l"(r) : "l"(a), "l"(b), "l"(c));
    return r;
}
__device__ __forceinline__ unsigned long long add2(unsigned long long a,
                                                   unsigned long long b) {
    unsigned long long r;
    asm("add.rn.f32x2 %0, %1, %2;" : "=l"(r) : "l"(a), "l"(b));
    return r;
}

// 4 distances, packed: d[i] = ax*x + ay*y + az*z + (w + qw)  (bit-identical to scalar rn)
__device__ __forceinline__ void dist4(const float* __restrict__ xs,
                                      const float* __restrict__ ys,
                                      const float* __restrict__ zs,
                                      const float* __restrict__ ws, int j0,
                                      unsigned long long ax2, unsigned long long ay2,
                                      unsigned long long az2, unsigned long long qw2,
                                      float d[4]) {
    ulonglong2 X = *(const ulonglong2*)(xs + j0);
    ulonglong2 Y = *(const ulonglong2*)(ys + j0);
    ulonglong2 Z = *(const ulonglong2*)(zs + j0);
    ulonglong2 W = *(const ulonglong2*)(ws + j0);
    unsigned long long t0 = fma2(az2, Z.x, add2(W.x, qw2));
    t0 = fma2(ay2, Y.x, t0);
    t0 = fma2(ax2, X.x, t0);
    unsigned long long t1 = fma2(az2, Z.y, add2(W.y, qw2));
    t1 = fma2(ay2, Y.y, t1);
    t1 = fma2(ax2, X.y, t1);
    unpack2(t0, d[0], d[1]);
    unpack2(t1, d[2], d[3]);
}

// ----- u32 compare-exchange: a=min, b=max -----
__device__ __forceinline__ void cx(unsigned& a, unsigned& b) {
    unsigned lo = min(a, b);
    b = max(a, b);
    a = lo;
}

// Batcher odd-even mergesort n=8 (19 CE), ascending
__device__ __forceinline__ void sort8(unsigned k[8]) {
    cx(k[0],k[1]); cx(k[2],k[3]); cx(k[4],k[5]); cx(k[6],k[7]);
    cx(k[0],k[2]); cx(k[1],k[3]); cx(k[4],k[6]); cx(k[5],k[7]);
    cx(k[1],k[2]); cx(k[5],k[6]);
    cx(k[0],k[4]); cx(k[1],k[5]); cx(k[2],k[6]); cx(k[3],k[7]);
    cx(k[2],k[4]); cx(k[3],k[5]);
    cx(k[1],k[2]); cx(k[3],k[4]); cx(k[5],k[6]);
}

// bitonic cleaner len 8 (12 CE)
__device__ __forceinline__ void clean8(unsigned k[8]) {
    cx(k[0],k[4]); cx(k[1],k[5]); cx(k[2],k[6]); cx(k[3],k[7]);
    cx(k[0],k[2]); cx(k[1],k[3]); cx(k[4],k[6]); cx(k[5],k[7]);
    cx(k[0],k[1]); cx(k[2],k[3]); cx(k[4],k[5]); cx(k[6],k[7]);
}

// bitonic cleaner len 16 (32 CE)
__device__ __forceinline__ void clean16(unsigned k[16]) {
#pragma unroll
    for (int j = 8; j; j >>= 1)
#pragma unroll
        for (int i = 0; i < 16; ++i) {
            int l = i ^ j;
            if (l > i) cx(k[i], k[l]);
        }
}

// 2-way serial merge of sorted u32 lists -> 16 smallest
#define MRGU(SRC_A, SRC_B, LEN, DSTSTMT)                                      \
    {                                                                         \
        int ii = 0, jj = 0;                                                   \
        _Pragma("unroll 1")                                                   \
        for (int r = 0; r < 16; ++r) {                                        \
            unsigned a = (SRC_A)[min(ii, (LEN) - 1)];                         \
            unsigned b = (SRC_B)[min(jj, (LEN) - 1)];                         \
            bool takeA = (jj >= (LEN)) || ((ii < (LEN)) && (a <= b));         \
            unsigned o = takeA ? a : b;                                       \
            ii += takeA; jj += !takeA;                                        \
            DSTSTMT;                                                          \
        }                                                                     \
    }

// ================= Kernel A: tau estimate + exhaustive filter =================
extern "C" __global__ void __launch_bounds__(KTH, 2)
knn_kernel(const float* __restrict__ coords) {
    extern __shared__ unsigned char sraw[];
    float* xs = (float*)sraw;                  // SoA staging, 4 x 16KB
    float* ys = xs + PASS_CANDS;
    float* zs = ys + PASS_CANDS;
    float* ws = zs + PASS_CANDS;
    unsigned* tau_sm = (unsigned*)(sraw + PASS_CANDS * 16);   // [QPB]

    const int tid = threadIdx.x;
    const int cloud = blockIdx.x >> 7;
    const int qblk = blockIdx.x & 127;
    const int qLocal = tid & (QPB - 1);
    const int split = tid >> 6;            // warp-uniform

    const float* cb = coords + (size_t)cloud * Mc * 3;
    const int q = qblk * QPB + qLocal;
    const int gq = cloud * Mc + q;

    const float qx = cb[3 * q], qy = cb[3 * q + 1], qz = cb[3 * q + 2];
    const float qw = fmaf(qx, qx, fmaf(qy, qy, qz * qz));
    const float ax = -2.0f * qx, ay = -2.0f * qy, az = -2.0f * qz;
    const unsigned long long ax2 = pack2(ax), ay2 = pack2(ay),
                             az2 = pack2(az), qw2 = pack2(qw);
    const int sbase = split << 9;          // slice base within window

    // ---------- Phase A: keep-8 over contiguous-64-per-slice subsample ----------
    unsigned tk[8];
#pragma unroll
    for (int t = 0; t < 8; ++t) tk[t] = 0xFFFFFFFFu;

#pragma unroll 1
    for (int pass = 0; pass < 2; ++pass) {
        __syncthreads();
        const int wbase = pass * PASS_CANDS;
        for (int i = tid; i < PASS_CANDS; i += KTH) {
            const int jg = wbase + i;
            float x = cb[3 * jg], y = cb[3 * jg + 1], z = cb[3 * jg + 2];
            xs[i] = x; ys[i] = y; zs[i] = z;
            ws[i] = fmaf(x, x, fmaf(y, y, z * z));
        }
        __syncthreads();

#pragma unroll 1
        for (int b = 0; b < 8; ++b) {
            const int j0 = sbase + b * 8;
            float dv[8];
            dist4(xs, ys, zs, ws, j0,     ax2, ay2, az2, qw2, dv);
            dist4(xs, ys, zs, ws, j0 + 4, ax2, ay2, az2, qw2, dv + 4);
            unsigned bk[8];
#pragma unroll
            for (int i = 0; i < 8; ++i)
                bk[i] = (__float_as_uint(dv[i]) & 0x7FFFF800u) | (unsigned)(b * 8 + i);
            sort8(bk);
#pragma unroll
            for (int i = 0; i < 8; ++i) tk[i] = min(tk[i], bk[7 - i]);
            clean8(tk);
        }
    }

    // ---------- merge 8 sorted-8 keys -> 16th smallest -> tau ----------
    __syncthreads();
    unsigned* bufA = (unsigned*)sraw;      // [QPB*68] (overlays staging)
    unsigned* bufB = bufA + QPB * 68;      // [QPB*68]
    const int rowA = qLocal * 68 + split * 8;
#pragma unroll
    for (int t = 0; t < 8; ++t) bufA[rowA + t] = tk[t];
    __syncthreads();

    if (split < 4) {
        const unsigned* sa = bufA + qLocal * 68 + split * 16;
        unsigned* dst = bufB + qLocal * 68 + split * 16;
        MRGU(sa, sa + 8, 8, dst[r] = o);
    }
    __syncthreads();
    if (split < 2) {
        const unsigned* sa = bufB + qLocal * 68 + split * 32;
        unsigned* dst = bufA + qLocal * 68 + split * 16;
        MRGU(sa, sa + 16, 16, dst[r] = o);
    }
    __syncthreads();
    if (split == 0) {
        const unsigned* sa = bufA + qLocal * 68;
        unsigned last = 0;
        MRGU(sa, sa + 16, 16, last = o);
        tau_sm[qLocal] = last | 0x7FFu;    // bin-top: valid upper bound of d16
    }
    __syncthreads();
    const float tauf = __uint_as_float(tau_sm[qLocal]);

    // ---------- Phase B: exhaustive packed filter ----------
    int cnt = 0;
    unsigned* seg = &g_survk[gq][split][0];
#pragma unroll 1
    for (int pass = 0; pass < 2; ++pass) {
        __syncthreads();
        const int wbase = pass * PASS_CANDS;
        for (int i = tid; i < PASS_CANDS; i += KTH) {
            const int jg = wbase + i;
            float x = cb[3 * jg], y = cb[3 * jg + 1], z = cb[3 * jg + 2];
            xs[i] = x; ys[i] = y; zs[i] = z;
            ws[i] = fmaf(x, x, fmaf(y, y, z * z));
        }
        __syncthreads();

        const int gbase = wbase + sbase;
#pragma unroll 2
        for (int j0 = 0; j0 < 512; j0 += 4) {
            float dv[4];
            dist4(xs, ys, zs, ws, sbase + j0, ax2, ay2, az2, qw2, dv);
#pragma unroll
            for (int i = 0; i < 4; ++i) {
                if (dv[i] <= tauf) {
                    if (cnt < SCAP)
                        seg[cnt] = (__float_as_uint(dv[i]) & 0x7FFFE000u)
                                 | (unsigned)(gbase + j0 + i);
                    ++cnt;
                }
            }
        }
    }
    g_cnt[gq][split] = cnt;
}

// ====== select: top-16 of survivors (8 threads/query) + fused losses ======
extern "C" __global__ void __launch_bounds__(KTH, 1)
select_kernel(const float* __restrict__ scores, const float* __restrict__ coords) {
    extern __shared__ unsigned char sraw[];
    unsigned* bufA = (unsigned*)sraw;              // [QPB][136]
    unsigned* bufB = bufA + QPB * 136;             // [QPB][68]
    int* ovf = (int*)(bufB + QPB * 68);            // [QPB]
    __shared__ double red[16][6];

    const int tid = threadIdx.x;
    const int qLocal = tid & (QPB - 1);
    const int split = tid >> 6;
    const int gq = blockIdx.x * QPB + qLocal;
    const int goff = (gq >> 13) << 13;

    if (split == 0) ovf[qLocal] = 0;
    __syncthreads();

    int cn = g_cnt[gq][split];
    if (cn > SCAP) { ovf[qLocal] = 1; cn = SCAP; }
    const unsigned* seg = &g_survk[gq][split][0];

    unsigned tk[16];
#pragma unroll
    for (int t = 0; t < 16; ++t) tk[t] = 0xFFFFFFFFu;

#pragma unroll 1
    for (int k = 0; k < cn; k += 8) {
        unsigned bk[8];
#pragma unroll
        for (int i = 0; i < 8; ++i)
            bk[i] = (k + i < cn) ? seg[k + i] : 0xFFFFFFFFu;
        sort8(bk);
#pragma unroll
        for (int i = 0; i < 8; ++i) tk[15 - i] = min(tk[15 - i], bk[i]);
        clean16(tk);
    }

    const int rowA = qLocal * 136 + split * 16;
#pragma unroll
    for (int t = 0; t < 16; ++t) bufA[rowA + t] = tk[t];
    __syncthreads();

    if (split < 4) {   // round 1: 8 sorted-16 -> 4
        const unsigned* sa = bufA + qLocal * 136 + split * 32;
        unsigned* dst = bufB + qLocal * 68 + split * 16;
        MRGU(sa, sa + 16, 16, dst[r] = o);
    }
    __syncthreads();
    if (split < 2) {   // round 2: 4 -> 2
        const unsigned* sa = bufB + qLocal * 68 + split * 32;
        unsigned* dst = bufA + qLocal * 136 + split * 16;
        MRGU(sa, sa + 16, 16, dst[r] = o);
    }
    __syncthreads();

    double acc[6] = {0, 0, 0, 0, 0, 0};
    if (split == 0) {  // round 3: final 16, write + fused loss
        int* out = g_knn + (size_t)gq * KF;
        const unsigned* sa = bufA + qLocal * 136;
        unsigned* nbrow = bufB + qLocal * 68;      // bufB free after round 2
        MRGU(sa, sa + 16, 16, {
            unsigned gi = o & 0x1FFFu;
            out[r] = goff + (int)gi;
            nbrow[r] = gi;
        });
        if (ovf[qLocal]) {
            int slot = atomicAdd(&g_nflag, 1);
            g_flagq[slot] = gq;
        } else {
            const float si = scores[gq];
            const float xi = coords[3 * gq], yi = coords[3 * gq + 1], zi = coords[3 * gq + 2];
            float nsum = 0.0f;
#pragma unroll
            for (int r = 0; r < KF; ++r) {
                const int n = goff + (int)nbrow[r];
                const float sn = scores[n];
                const float sd = fabsf(si - sn);
                const float x = (1.0f - sd) * 2.0f;
                const float sig = 1.0f / (1.0f + expf(-x));
                if (r < KN) {
                    const float dx = xi - coords[3 * n];
                    const float dy = yi - coords[3 * n + 1];
                    const float dz = zi - coords[3 * n + 2];
                    const float dist = sqrtf(dx * dx + dy * dy + dz * dz);
                    const float w = expf(-dist * 10.0f);
                    acc[0] += (double)(w * sd * sd);
                    acc[1] += (double)w;
                    acc[2] += (double)logf(sig + 1e-8f);
                    nsum += sn;
                } else {
                    acc[3] += (double)logf(1.0f - sig + 1e-8f);
                }
            }
            const float dm = si - nsum * 0.125f;
            acc[4] = (double)(dm * dm);

            const int cloud = gq >> 13;
            const int local = gq & (Mc - 1);
            int b = (int)(si * (float)NB);
            b = b < 0 ? 0 : (b > NB - 1 ? NB - 1 : b);
            int hcnt = g_hist[cloud][b];
            hcnt = hcnt > BCAP ? BCAP : hcnt;
            int rk = 0;
            const int* mem = &g_members[cloud][b * BCAP];
            for (int k = 0; k < hcnt; ++k) {
                const int m = mem[k];
                const float sm = scores[(cloud << 13) + m];
                rk += (sm < si) || (sm == si && m < local);
            }
            const int rank = g_pref[cloud][b] + rk;
            const float df = si - (float)rank * (1.0f / (float)(Mc - 1));
            acc[5] = (double)(df * df);
        }
    }

    // block reduce 6 terms over all 512 threads
    const int lane = threadIdx.x & 31;
    const int wid = threadIdx.x >> 5;
#pragma unroll
    for (int k = 0; k < 6; ++k)
#pragma unroll
        for (int o = 16; o; o >>= 1)
            acc[k] += __shfl_down_sync(0xffffffffu, acc[k], o);
    if (lane == 0)
#pragma unroll
        for (int k = 0; k < 6; ++k) red[wid][k] = acc[k];
    __syncthreads();
    if (wid == 0 && lane < 6) {
        double s = 0.0;
#pragma unroll
        for (int w = 0; w < 16; ++w) s += red[w][lane];
        atomicAdd(&g_acc[lane], s);
    }
}

// ============ exact fallback for overflowed queries (rare) + loss ============
#define FB_BLOCKS 296
#define FB_WARPS 8
__global__ void __launch_bounds__(FB_WARPS * 32)
fallback_kernel(const float* __restrict__ coords, const float* __restrict__ scores) {
    __shared__ unsigned S[FB_WARPS][32][17];
    const int w = threadIdx.x >> 5;
    const int lane = threadIdx.x & 31;
    const int nf = g_nflag;

    for (int f = blockIdx.x * FB_WARPS + w; f < nf; f += FB_BLOCKS * FB_WARPS) {
        const int gq = g_flagq[f];
        const int cloud = gq >> 13;
        const int q = gq & (Mc - 1);
        const float* cb = coords + (size_t)cloud * Mc * 3;
        const float4* cp = (const float4*)cb;
        const float qx = cb[3 * q], qy = cb[3 * q + 1], qz = cb[3 * q + 2];

        unsigned tk[16];
#pragma unroll
        for (int t = 0; t < 16; ++t) tk[t] = 0xFFFFFFFFu;

#pragma unroll 1
        for (int b = 0; b < 32; ++b) {
            const int j0 = lane * 256 + b * 8;
            const float4* p = cp + ((3 * j0) >> 2);
            float4 A = p[0], Bv = p[1], C = p[2], D = p[3], E = p[4], F = p[5];
            float xs[8] = {A.x, A.w, Bv.z, C.y, D.x, D.w, E.z, F.y};
            float ys[8] = {A.y, Bv.x, Bv.w, C.z, D.y, E.x, E.w, F.z};
            float zs[8] = {A.z, Bv.y, C.x, C.w, D.z, E.y, F.x, F.w};
            unsigned bk[8];
#pragma unroll
            for (int i = 0; i < 8; ++i) {
                float dx = xs[i] - qx, dy = ys[i] - qy, dz = zs[i] - qz;
                float d = fmaf(dz, dz, fmaf(dy, dy, dx * dx));
                bk[i] = (__float_as_uint(d) & 0xFFFFE000u) | (unsigned)(j0 + i);
            }
            sort8(bk);
#pragma unroll
            for (int i = 0; i < 8; ++i) tk[15 - i] = min(tk[15 - i], bk[i]);
            clean16(tk);
        }

#pragma unroll
        for (int t = 0; t < 16; ++t) S[w][lane][t] = tk[t];
        __syncwarp();
#pragma unroll
        for (int s = 1; s < 32; s <<= 1) {
            if ((lane & (2 * s - 1)) == 0) {
                unsigned ok[16];
#pragma unroll
                for (int t = 0; t < 16; ++t) ok[t] = S[w][lane + s][t];
#pragma unroll
                for (int t = 0; t < 16; ++t) tk[t] = min(tk[t], ok[15 - t]);
                clean16(tk);
#pragma unroll
                for (int t = 0; t < 16; ++t) S[w][lane][t] = tk[t];
            }
            __syncwarp();
        }
        if (lane == 0) {
            int* out = g_knn + (size_t)gq * KF;
            const int goff = cloud * Mc;
#pragma unroll
            for (int t = 0; t < 16; ++t) out[t] = goff + (int)(tk[t] & 0x1FFFu);

            // fused loss for this (flagged) query
            double acc[6] = {0, 0, 0, 0, 0, 0};
            const float si = scores[gq];
            const float xi = cb[3 * q], yi = cb[3 * q + 1], zi = cb[3 * q + 2];
            float nsum = 0.0f;
#pragma unroll
            for (int r = 0; r < KF; ++r) {
                const int n = goff + (int)(tk[r] & 0x1FFFu);
                const float sn = scores[n];
                const float sd = fabsf(si - sn);
                const float x = (1.0f - sd) * 2.0f;
                const float sig = 1.0f / (1.0f + expf(-x));
                if (r < KN) {
                    const float dx = xi - coords[3 * n];
                    const float dy = yi - coords[3 * n + 1];
                    const float dz = zi - coords[3 * n + 2];
                    const float dist = sqrtf(dx * dx + dy * dy + dz * dz);
                    const float wv = expf(-dist * 10.0f);
                    acc[0] += (double)(wv * sd * sd);
                    acc[1] += (double)wv;
                    acc[2] += (double)logf(sig + 1e-8f);
                    nsum += sn;
                } else {
                    acc[3] += (double)logf(1.0f - sig + 1e-8f);
                }
            }
            const float dm = si - nsum * 0.125f;
            acc[4] = (double)(dm * dm);

            int b = (int)(si * (float)NB);
            b = b < 0 ? 0 : (b > NB - 1 ? NB - 1 : b);
            int hcnt = g_hist[cloud][b];
            hcnt = hcnt > BCAP ? BCAP : hcnt;
            int rk = 0;
            const int* mem = &g_members[cloud][b * BCAP];
            for (int k = 0; k < hcnt; ++k) {
                const int m = mem[k];
                const float sm = scores[(cloud << 13) + m];
                rk += (sm < si) || (sm == si && m < q);
            }
            const int rank = g_pref[cloud][b] + rk;
            const float df = si - (float)rank * (1.0f / (float)(Mc - 1));
            acc[5] = (double)(df * df);
#pragma unroll
            for (int k = 0; k < 6; ++k) atomicAdd(&g_acc[k], acc[k]);
        }
        __syncwarp();
    }
}

// ================= rank bucketing (exact, replaces sort) =================
__global__ void zero_kernel() {
    const int t = blockIdx.x * blockDim.x + threadIdx.x;
    if (t < 8) g_acc[t] = 0.0;
    if (t == 8) g_nflag = 0;
    for (int i = t; i < Bc * NB; i += gridDim.x * blockDim.x)
        ((int*)g_hist)[i] = 0;
}

__global__ void rank_build_kernel(const float* __restrict__ scores) {
    const int i = blockIdx.x * blockDim.x + threadIdx.x;
    if (i >= Nc) return;
    const int cloud = i >> 13;
    const int local = i & (Mc - 1);
    const float s = scores[i];
    int b = (int)(s * (float)NB);
    b = b < 0 ? 0 : (b > NB - 1 ? NB - 1 : b);
    const int slot = atomicAdd(&g_hist[cloud][b], 1);
    if (slot < BCAP) g_members[cloud][b * BCAP + slot] = local;
}

__global__ void prefix_kernel() {
    __shared__ int sc[1024];
    const int cloud = blockIdx.x;
    const int t = threadIdx.x;
    const int base = t * 4;
    int h0 = g_hist[cloud][base + 0];
    int h1 = g_hist[cloud][base + 1];
    int h2 = g_hist[cloud][base + 2];
    int h3 = g_hist[cloud][base + 3];
    int sum = h0 + h1 + h2 + h3;
    sc[t] = sum;
    __syncthreads();
    for (int off = 1; off < 1024; off <<= 1) {
        int v = (t >= off) ? sc[t - off] : 0;
        __syncthreads();
        sc[t] += v;
        __syncthreads();
    }
    int excl = sc[t] - sum;
    g_pref[cloud][base + 0] = excl; excl += h0;
    g_pref[cloud][base + 1] = excl; excl += h1;
    g_pref[cloud][base + 2] = excl; excl += h2;
    g_pref[cloud][base + 3] = excl;
}

// ================= finalize =================
__global__ void finalize_kernel(float* out) {
    const double l_loc = g_acc[0] / fmax(g_acc[1], 1e-8);
    const double l_pos = -g_acc[2] / (double)((size_t)Nc * KN);
    const double l_neg = -g_acc[3] / (double)((size_t)Nc * KN);
    const double l_con = l_pos + l_neg;
    const double l_smooth = g_acc[4] / (double)Nc;
    const double l_dist = g_acc[5] / (double)Nc;
    out[0] = (float)(1.0 * l_loc + 0.5 * l_con + 0.3 * l_dist + 0.2 * l_smooth);
}

extern "C" void kernel_launch(void* const* d_in, const int* in_sizes, int n_in,
                              void* d_out, int out_size) {
    const float* scores = (const float*)d_in[0];
    const float* coords = (const float*)d_in[1];
    (void)in_sizes; (void)n_in; (void)out_size;

    const int KNN_SMEM = PASS_CANDS * 16 + QPB * (int)sizeof(unsigned) + 128;
    cudaFuncSetAttribute(knn_kernel,
                         cudaFuncAttributeMaxDynamicSharedMemorySize, KNN_SMEM);
    const int SEL_SMEM = (QPB * 136 + QPB * 68) * (int)sizeof(unsigned)
                       + QPB * (int)sizeof(int);
    cudaFuncSetAttribute(select_kernel,
                         cudaFuncAttributeMaxDynamicSharedMemorySize, SEL_SMEM);

    zero_kernel<<<16, 1024>>>();
    rank_build_kernel<<<Nc / 256, 256>>>(scores);
    prefix_kernel<<<Bc, 1024>>>();
    knn_kernel<<<Bc * QBLKS, KTH, KNN_SMEM>>>(coords);
    select_kernel<<<Nc / QPB, KTH, SEL_SMEM>>>(scores, coords);
    fallback_kernel<<<FB_BLOCKS, FB_WARPS * 32>>>(coords, scores);
    finalize_kernel<<<1, 1>>>((float*)d_out);
}